// round 2
// baseline (speedup 1.0000x reference)
#include <cuda_runtime.h>
#include <math.h>

// ---------------- problem constants ----------------
#define BB   16     // batch
#define NN   24     // boxes per image
#define CC   149    // channels: 1 obj + 2 xy + 2 wh + 4 head + 120 + 8 + 12
#define NBC  120
#define NEC  8
#define NAC  12
#define IGN_V (-100)
#define IMG  640.0f

#define L_OBJ  1.0f
#define L_BOX  5.0f
#define L_HEAD 2.0f
#define L_ATTR 1.0f

#define NBLK1 256   // blocks for obj-softplus reduction (fixed -> deterministic)
#define NBLK2 48    // 3 scales * 16 batch

// scratch (no allocations allowed -> device globals)
__device__ float g_obj_partial[NBLK1];
__device__ float g_loss_partial[NBLK2];
__device__ int   g_pos_partial[NBLK2];

__device__ __forceinline__ float softplusf(float x) {
    // jax.nn.softplus = max(x,0) + log1p(exp(-|x|))
    return fmaxf(x, 0.f) + log1pf(expf(-fabsf(x)));
}
__device__ __forceinline__ float sigm(float x) { return 1.f / (1.f + expf(-x)); }
__device__ __forceinline__ float sl1(float p, float t) {
    float d = fabsf(p - t);
    return d < 1.f ? 0.5f * d * d : d - 0.5f;
}

// ---------------------------------------------------------------------------
// Kernel 1: sum of softplus(pred[...,0]) over all cells of all 3 scales.
// Deterministic: fixed grid, fixed-slot partials, tree reduction.
// ---------------------------------------------------------------------------
__global__ void obj_sum_kernel(const float* __restrict__ p0,
                               const float* __restrict__ p1,
                               const float* __restrict__ p2) {
    const int T0 = BB * 80 * 80;
    const int T1 = BB * 40 * 40;
    const int T2 = BB * 20 * 20;
    const int total = T0 + T1 + T2;

    float acc = 0.f;
    for (int i = blockIdx.x * blockDim.x + threadIdx.x; i < total;
         i += gridDim.x * blockDim.x) {
        const float* p;
        int loc;
        if (i < T0)            { p = p0; loc = i; }
        else if (i < T0 + T1)  { p = p1; loc = i - T0; }
        else                   { p = p2; loc = i - T0 - T1; }
        float x = __ldg(p + (size_t)loc * CC);
        acc += softplusf(x);
    }

    __shared__ float sh[256];
    int tid = threadIdx.x;
    sh[tid] = acc;
    __syncthreads();
    for (int s = 128; s > 0; s >>= 1) {
        if (tid < s) sh[tid] += sh[tid + s];
        __syncthreads();
    }
    if (tid == 0) g_obj_partial[blockIdx.x] = sh[0];
}

// ---------------------------------------------------------------------------
// Kernel 2: per (scale, batch-row): winner assignment + all winner-only losses.
// One block per (scale,b). 256 threads = 8 warps; warp w handles boxes w,w+8,w+16.
// ---------------------------------------------------------------------------
__global__ void winner_loss_kernel(const float* __restrict__ p0,
                                   const float* __restrict__ p1,
                                   const float* __restrict__ p2,
                                   const float* __restrict__ body,
                                   const float* __restrict__ headb,
                                   const int*   __restrict__ labels,
                                   const int*   __restrict__ emotions,
                                   const int*   __restrict__ actions,
                                   const int*   __restrict__ head_valid) {
    const int s = blockIdx.x / BB;
    const int b = blockIdx.x % BB;
    const float* pred = (s == 0) ? p0 : ((s == 1) ? p1 : p2);
    const int   H  = (s == 0) ? 80 : ((s == 1) ? 40 : 20);
    const int   W  = H;
    const float sx = IMG / (float)W;
    const float sy = IMG / (float)H;

    __shared__ float sX1[NN], sY1[NN], sBW[NN], sBH[NN], sCX[NN], sCY[NN], sArea[NN];
    __shared__ int   sGX[NN], sGY[NN], sRank[NN];
    __shared__ unsigned char sValid[NN], sWin[NN];

    const int tid  = threadIdx.x;
    const int warp = tid >> 5;
    const int lane = tid & 31;

    if (tid < NN) {
        const float* bx = body + ((size_t)b * NN + tid) * 4;
        float r0 = bx[0], r1 = bx[1], r2 = bx[2], r3 = bx[3];
        float mx = fmaxf(fmaxf(r0, r1), fmaxf(r2, r3));
        float sc = (mx <= 1.5f) ? IMG : 1.f;      // _scale_box
        float x1 = r0 * sc, y1 = r1 * sc, x2 = r2 * sc, y2 = r3 * sc;
        float bw = x2 - x1, bh = y2 - y1;
        float cx = 0.5f * (x1 + x2), cy = 0.5f * (y1 + y2);
        int gx = (int)floorf(cx / sx);
        int gy = (int)floorf(cy / sy);
        bool valid = (bw > 0.f) && (bh > 0.f) && (gx >= 0) && (gy >= 0) &&
                     (gx < W) && (gy < H);
        // area from UNSCALED boxes
        sArea[tid]  = fmaxf(r2 - r0, 0.f) * fmaxf(r3 - r1, 0.f);
        sX1[tid] = x1; sY1[tid] = y1;
        sBW[tid] = bw; sBH[tid] = bh;
        sCX[tid] = cx; sCY[tid] = cy;
        sGX[tid] = min(max(gx, 0), W - 1);
        sGY[tid] = min(max(gy, 0), H - 1);
        sValid[tid] = valid ? 1 : 0;
    }
    __syncthreads();

    if (tid < NN) {
        // stable ascending argsort rank (double-argsort equivalent)
        float ai = sArea[tid];
        int r = 0;
        #pragma unroll
        for (int j = 0; j < NN; j++) {
            float aj = sArea[j];
            if (aj < ai || (aj == ai && j < tid)) r++;
        }
        sRank[tid] = r;
    }
    __syncthreads();

    if (tid < NN) {
        bool win = sValid[tid] != 0;
        if (win) {
            int gx = sGX[tid], gy = sGY[tid], ri = sRank[tid];
            #pragma unroll
            for (int j = 0; j < NN; j++) {
                if (sValid[j] && sGX[j] == gx && sGY[j] == gy && sRank[j] < ri)
                    win = false;
            }
        }
        sWin[tid] = win ? 1 : 0;
    }
    __syncthreads();

    float wloss = 0.f;
    int   wpos  = 0;

    for (int n = warp; n < NN; n += 8) {
        if (!sWin[n]) continue;

        const float* cp = pred +
            (((size_t)b * H + sGY[n]) * W + sGX[n]) * CC;

        // ---- body-class log-softmax over 120 channels (warp-parallel) ----
        float v[4];
        float mx = -1e30f;
        #pragma unroll
        for (int k = 0; k < 4; k++) {
            int j = lane + 32 * k;
            v[k] = (j < NBC) ? cp[9 + j] : -1e30f;
            mx = fmaxf(mx, v[k]);
        }
        #pragma unroll
        for (int off = 16; off > 0; off >>= 1)
            mx = fmaxf(mx, __shfl_xor_sync(0xffffffffu, mx, off));
        float se = 0.f;
        #pragma unroll
        for (int k = 0; k < 4; k++) {
            int j = lane + 32 * k;
            if (j < NBC) se += expf(v[k] - mx);
        }
        #pragma unroll
        for (int off = 16; off > 0; off >>= 1)
            se += __shfl_xor_sync(0xffffffffu, se, off);

        if (lane == 0) {
            wpos++;
            float lzB = mx + logf(se);

            // body-class CE
            float ce_b = 0.f;
            int lab = labels[b * NN + n];
            if (lab != IGN_V) {
                int t = min(max(lab, 0), NBC - 1);
                ce_b = -(cp[9 + t] - lzB);
            }
            // emotion CE (8)
            float m2 = -1e30f;
            for (int j = 0; j < NEC; j++) m2 = fmaxf(m2, cp[9 + NBC + j]);
            float s2 = 0.f;
            for (int j = 0; j < NEC; j++) s2 += expf(cp[9 + NBC + j] - m2);
            float ce_e = 0.f;
            int em = emotions[b * NN + n];
            if (em != IGN_V) {
                int t = min(max(em, 0), NEC - 1);
                ce_e = -(cp[9 + NBC + t] - m2 - logf(s2));
            }
            // action CE (12)
            float m3 = -1e30f;
            for (int j = 0; j < NAC; j++) m3 = fmaxf(m3, cp[9 + NBC + NEC + j]);
            float s3 = 0.f;
            for (int j = 0; j < NAC; j++) s3 += expf(cp[9 + NBC + NEC + j] - m3);
            float ce_a = 0.f;
            int ac = actions[b * NN + n];
            if (ac != IGN_V) {
                int t = min(max(ac, 0), NAC - 1);
                ce_a = -(cp[9 + NBC + NEC + t] - m3 - logf(s3));
            }

            // ---- box loss ----
            float tx = sCX[n] / sx - (float)sGX[n];
            float ty = sCY[n] / sy - (float)sGY[n];
            float tw = logf(sBW[n] / sx + 1e-6f);
            float th = logf(sBH[n] / sy + 1e-6f);
            float box_l = sl1(sigm(cp[1]), tx) + sl1(sigm(cp[2]), ty) +
                          sl1(cp[3], tw)       + sl1(cp[4], th);

            // ---- head loss ----
            float head_l = 0.f;
            {
                const float* hb = headb + ((size_t)b * NN + n) * 4;
                float h0 = hb[0], h1 = hb[1], h2 = hb[2], h3 = hb[3];
                float hm = fmaxf(fmaxf(h0, h1), fmaxf(h2, h3));
                float hc = (hm <= 1.5f) ? IMG : 1.f;
                float hx1 = h0 * hc, hy1 = h1 * hc, hx2 = h2 * hc, hy2 = h3 * hc;
                bool hmask = (head_valid[b * NN + n] != 0) &&
                             (hx2 > hx1) && (hy2 > hy1);
                if (hmask) {
                    float bw = sBW[n], bh = sBH[n];
                    float q0 = fminf(fmaxf((hx1 - sX1[n]) / bw, 0.f), 1.f);
                    float q1 = fminf(fmaxf((hy1 - sY1[n]) / bh, 0.f), 1.f);
                    float q2 = fminf(fmaxf((hx2 - sX1[n]) / bw, 0.f), 1.f);
                    float q3 = fminf(fmaxf((hy2 - sY1[n]) / bh, 0.f), 1.f);
                    head_l = sl1(sigm(cp[5]), q0) + sl1(sigm(cp[6]), q1) +
                             sl1(sigm(cp[7]), q2) + sl1(sigm(cp[8]), q3);
                }
            }

            // winner contribution; -obj accounts for -obj*obj_target in BCE
            wloss += L_BOX * box_l + L_HEAD * head_l +
                     L_ATTR * (ce_b + ce_e + ce_a) - L_OBJ * cp[0];
        }
    }

    // deterministic block reduction over the 8 warps
    __shared__ float shl[8];
    __shared__ int   shp[8];
    if (lane == 0) { shl[warp] = wloss; shp[warp] = wpos; }
    __syncthreads();
    if (tid == 0) {
        float L = 0.f; int P = 0;
        #pragma unroll
        for (int w = 0; w < 8; w++) { L += shl[w]; P += shp[w]; }
        g_loss_partial[blockIdx.x] = L;
        g_pos_partial[blockIdx.x]  = P;
    }
}

// ---------------------------------------------------------------------------
// Kernel 3: deterministic final combine.
// ---------------------------------------------------------------------------
__global__ void finalize_kernel(float* __restrict__ out) {
    __shared__ float sh[NBLK1];
    int tid = threadIdx.x;
    sh[tid] = g_obj_partial[tid];
    __syncthreads();
    for (int s = NBLK1 / 2; s > 0; s >>= 1) {
        if (tid < s) sh[tid] += sh[tid + s];
        __syncthreads();
    }
    if (tid == 0) {
        float total = L_OBJ * sh[0];
        int pos = 0;
        #pragma unroll
        for (int i = 0; i < NBLK2; i++) {
            total += g_loss_partial[i];
            pos   += g_pos_partial[i];
        }
        out[0] = total / (float)max(pos, 1);
    }
}

// ---------------------------------------------------------------------------
extern "C" void kernel_launch(void* const* d_in, const int* in_sizes, int n_in,
                              void* d_out, int out_size) {
    const float* p0       = (const float*)d_in[0];
    const float* p1       = (const float*)d_in[1];
    const float* p2       = (const float*)d_in[2];
    const float* body     = (const float*)d_in[3];
    const float* headb    = (const float*)d_in[4];
    const int*   labels   = (const int*)d_in[5];
    const int*   emotions = (const int*)d_in[6];
    const int*   actions  = (const int*)d_in[7];
    const int*   head_valid = (const int*)d_in[8];
    float* out = (float*)d_out;

    obj_sum_kernel<<<NBLK1, 256>>>(p0, p1, p2);
    winner_loss_kernel<<<NBLK2, 256>>>(p0, p1, p2, body, headb,
                                       labels, emotions, actions, head_valid);
    finalize_kernel<<<1, NBLK1>>>(out);
}

// round 3
// speedup vs baseline: 1.1366x; 1.1366x over previous
#include <cuda_runtime.h>
#include <math.h>

// ---------------- problem constants ----------------
#define BB   16     // batch
#define NN   24     // boxes per image
#define CC   149    // channels: 1 obj + 2 xy + 2 wh + 4 head + 120 + 8 + 12
#define NBC  120
#define NEC  8
#define NAC  12
#define IGN_V (-100)
#define IMG  640.0f

#define L_OBJ  1.0f
#define L_BOX  5.0f
#define L_HEAD 2.0f
#define L_ATTR 1.0f

#define T0_CELLS (BB * 80 * 80)   // 102400
#define T1_CELLS (BB * 40 * 40)   // 25600
#define T2_CELLS (BB * 20 * 20)   // 6400
#define TOT_CELLS (T0_CELLS + T1_CELLS + T2_CELLS)  // 134400

#define NWIN   48                  // 3 scales * 16 batch (winner-loss blocks)
#define NOBJ   (TOT_CELLS / 256)   // 525 obj blocks, 1 element/thread
#define NBLKS  (NWIN + NOBJ)       // 573

// scratch (no allocations allowed -> device globals)
__device__ float g_obj_partial[NOBJ];
__device__ float g_loss_partial[NWIN];
__device__ int   g_pos_partial[NWIN];
__device__ unsigned int g_done_count = 0;   // self-resetting -> graph-replay safe

__device__ __forceinline__ float softplusf(float x) {
    // jax.nn.softplus = max(x,0) + log1p(exp(-|x|))
    return fmaxf(x, 0.f) + log1pf(expf(-fabsf(x)));
}
__device__ __forceinline__ float sigm(float x) { return 1.f / (1.f + expf(-x)); }
__device__ __forceinline__ float sl1(float p, float t) {
    float d = fabsf(p - t);
    return d < 1.f ? 0.5f * d * d : d - 0.5f;
}

// ---------------------------------------------------------------------------
// Winner-loss role: one block per (scale, batch-row).
// ---------------------------------------------------------------------------
__device__ void winner_loss_block(int blk,
                                  const float* __restrict__ p0,
                                  const float* __restrict__ p1,
                                  const float* __restrict__ p2,
                                  const float* __restrict__ body,
                                  const float* __restrict__ headb,
                                  const int*   __restrict__ labels,
                                  const int*   __restrict__ emotions,
                                  const int*   __restrict__ actions,
                                  const int*   __restrict__ head_valid) {
    const int s = blk / BB;
    const int b = blk % BB;
    const float* pred = (s == 0) ? p0 : ((s == 1) ? p1 : p2);
    const int   H  = (s == 0) ? 80 : ((s == 1) ? 40 : 20);
    const int   W  = H;
    const float sx = IMG / (float)W;
    const float sy = IMG / (float)H;

    __shared__ float sX1[NN], sY1[NN], sBW[NN], sBH[NN], sCX[NN], sCY[NN], sArea[NN];
    __shared__ int   sGX[NN], sGY[NN], sRank[NN];
    __shared__ unsigned char sValid[NN], sWin[NN];

    const int tid  = threadIdx.x;
    const int warp = tid >> 5;
    const int lane = tid & 31;

    if (tid < NN) {
        const float* bx = body + ((size_t)b * NN + tid) * 4;
        float r0 = bx[0], r1 = bx[1], r2 = bx[2], r3 = bx[3];
        float mx = fmaxf(fmaxf(r0, r1), fmaxf(r2, r3));
        float sc = (mx <= 1.5f) ? IMG : 1.f;      // _scale_box
        float x1 = r0 * sc, y1 = r1 * sc, x2 = r2 * sc, y2 = r3 * sc;
        float bw = x2 - x1, bh = y2 - y1;
        float cx = 0.5f * (x1 + x2), cy = 0.5f * (y1 + y2);
        int gx = (int)floorf(cx / sx);
        int gy = (int)floorf(cy / sy);
        bool valid = (bw > 0.f) && (bh > 0.f) && (gx >= 0) && (gy >= 0) &&
                     (gx < W) && (gy < H);
        // area from UNSCALED boxes
        sArea[tid]  = fmaxf(r2 - r0, 0.f) * fmaxf(r3 - r1, 0.f);
        sX1[tid] = x1; sY1[tid] = y1;
        sBW[tid] = bw; sBH[tid] = bh;
        sCX[tid] = cx; sCY[tid] = cy;
        sGX[tid] = min(max(gx, 0), W - 1);
        sGY[tid] = min(max(gy, 0), H - 1);
        sValid[tid] = valid ? 1 : 0;
    }
    __syncthreads();

    if (tid < NN) {
        // stable ascending argsort rank (double-argsort equivalent)
        float ai = sArea[tid];
        int r = 0;
        #pragma unroll
        for (int j = 0; j < NN; j++) {
            float aj = sArea[j];
            if (aj < ai || (aj == ai && j < tid)) r++;
        }
        sRank[tid] = r;
    }
    __syncthreads();

    if (tid < NN) {
        bool win = sValid[tid] != 0;
        if (win) {
            int gx = sGX[tid], gy = sGY[tid], ri = sRank[tid];
            #pragma unroll
            for (int j = 0; j < NN; j++) {
                if (sValid[j] && sGX[j] == gx && sGY[j] == gy && sRank[j] < ri)
                    win = false;
            }
        }
        sWin[tid] = win ? 1 : 0;
    }
    __syncthreads();

    float wloss = 0.f;
    int   wpos  = 0;

    for (int n = warp; n < NN; n += 8) {
        if (!sWin[n]) continue;

        const float* cp = pred +
            (((size_t)b * H + sGY[n]) * W + sGX[n]) * CC;

        // ---- body-class log-softmax over 120 channels (warp-parallel) ----
        float v[4];
        float mx = -1e30f;
        #pragma unroll
        for (int k = 0; k < 4; k++) {
            int j = lane + 32 * k;
            v[k] = (j < NBC) ? cp[9 + j] : -1e30f;
            mx = fmaxf(mx, v[k]);
        }
        #pragma unroll
        for (int off = 16; off > 0; off >>= 1)
            mx = fmaxf(mx, __shfl_xor_sync(0xffffffffu, mx, off));
        float se = 0.f;
        #pragma unroll
        for (int k = 0; k < 4; k++) {
            int j = lane + 32 * k;
            if (j < NBC) se += expf(v[k] - mx);
        }
        #pragma unroll
        for (int off = 16; off > 0; off >>= 1)
            se += __shfl_xor_sync(0xffffffffu, se, off);

        if (lane == 0) {
            wpos++;
            float lzB = mx + logf(se);

            // body-class CE
            float ce_b = 0.f;
            int lab = labels[b * NN + n];
            if (lab != IGN_V) {
                int t = min(max(lab, 0), NBC - 1);
                ce_b = -(cp[9 + t] - lzB);
            }
            // emotion CE (8)
            float m2 = -1e30f;
            for (int j = 0; j < NEC; j++) m2 = fmaxf(m2, cp[9 + NBC + j]);
            float s2 = 0.f;
            for (int j = 0; j < NEC; j++) s2 += expf(cp[9 + NBC + j] - m2);
            float ce_e = 0.f;
            int em = emotions[b * NN + n];
            if (em != IGN_V) {
                int t = min(max(em, 0), NEC - 1);
                ce_e = -(cp[9 + NBC + t] - m2 - logf(s2));
            }
            // action CE (12)
            float m3 = -1e30f;
            for (int j = 0; j < NAC; j++) m3 = fmaxf(m3, cp[9 + NBC + NEC + j]);
            float s3 = 0.f;
            for (int j = 0; j < NAC; j++) s3 += expf(cp[9 + NBC + NEC + j] - m3);
            float ce_a = 0.f;
            int ac = actions[b * NN + n];
            if (ac != IGN_V) {
                int t = min(max(ac, 0), NAC - 1);
                ce_a = -(cp[9 + NBC + NEC + t] - m3 - logf(s3));
            }

            // ---- box loss ----
            float tx = sCX[n] / sx - (float)sGX[n];
            float ty = sCY[n] / sy - (float)sGY[n];
            float tw = logf(sBW[n] / sx + 1e-6f);
            float th = logf(sBH[n] / sy + 1e-6f);
            float box_l = sl1(sigm(cp[1]), tx) + sl1(sigm(cp[2]), ty) +
                          sl1(cp[3], tw)       + sl1(cp[4], th);

            // ---- head loss ----
            float head_l = 0.f;
            {
                const float* hb = headb + ((size_t)b * NN + n) * 4;
                float h0 = hb[0], h1 = hb[1], h2 = hb[2], h3 = hb[3];
                float hm = fmaxf(fmaxf(h0, h1), fmaxf(h2, h3));
                float hc = (hm <= 1.5f) ? IMG : 1.f;
                float hx1 = h0 * hc, hy1 = h1 * hc, hx2 = h2 * hc, hy2 = h3 * hc;
                bool hmask = (head_valid[b * NN + n] != 0) &&
                             (hx2 > hx1) && (hy2 > hy1);
                if (hmask) {
                    float bw = sBW[n], bh = sBH[n];
                    float q0 = fminf(fmaxf((hx1 - sX1[n]) / bw, 0.f), 1.f);
                    float q1 = fminf(fmaxf((hy1 - sY1[n]) / bh, 0.f), 1.f);
                    float q2 = fminf(fmaxf((hx2 - sX1[n]) / bw, 0.f), 1.f);
                    float q3 = fminf(fmaxf((hy2 - sY1[n]) / bh, 0.f), 1.f);
                    head_l = sl1(sigm(cp[5]), q0) + sl1(sigm(cp[6]), q1) +
                             sl1(sigm(cp[7]), q2) + sl1(sigm(cp[8]), q3);
                }
            }

            // winner contribution; -obj accounts for -obj*obj_target in BCE
            wloss += L_BOX * box_l + L_HEAD * head_l +
                     L_ATTR * (ce_b + ce_e + ce_a) - L_OBJ * cp[0];
        }
    }

    // deterministic block reduction over the 8 warps
    __shared__ float shl[8];
    __shared__ int   shp[8];
    if (lane == 0) { shl[warp] = wloss; shp[warp] = wpos; }
    __syncthreads();
    if (tid == 0) {
        float L = 0.f; int P = 0;
        #pragma unroll
        for (int w = 0; w < 8; w++) { L += shl[w]; P += shp[w]; }
        g_loss_partial[blk] = L;
        g_pos_partial[blk]  = P;
    }
}

// ---------------------------------------------------------------------------
// Fused kernel: blocks [0,48) do winner losses, blocks [48,573) do the obj
// softplus sum (1 cell/thread). Last block to finish combines everything.
// ---------------------------------------------------------------------------
__global__ void __launch_bounds__(256)
fused_loss_kernel(const float* __restrict__ p0,
                  const float* __restrict__ p1,
                  const float* __restrict__ p2,
                  const float* __restrict__ body,
                  const float* __restrict__ headb,
                  const int*   __restrict__ labels,
                  const int*   __restrict__ emotions,
                  const int*   __restrict__ actions,
                  const int*   __restrict__ head_valid,
                  float* __restrict__ out) {
    const int tid = threadIdx.x;

    if (blockIdx.x < NWIN) {
        winner_loss_block(blockIdx.x, p0, p1, p2, body, headb,
                          labels, emotions, actions, head_valid);
    } else {
        // obj role: exactly one cell per thread
        const int i = (blockIdx.x - NWIN) * 256 + tid;
        const float* p;
        int loc;
        if (i < T0_CELLS)                  { p = p0; loc = i; }
        else if (i < T0_CELLS + T1_CELLS)  { p = p1; loc = i - T0_CELLS; }
        else                               { p = p2; loc = i - T0_CELLS - T1_CELLS; }
        float acc = softplusf(__ldg(p + (size_t)loc * CC));

        __shared__ float sh[256];
        sh[tid] = acc;
        __syncthreads();
        #pragma unroll
        for (int s = 128; s > 0; s >>= 1) {
            if (tid < s) sh[tid] += sh[tid + s];
            __syncthreads();
        }
        if (tid == 0) g_obj_partial[blockIdx.x - NWIN] = sh[0];
    }

    // ---- completion protocol: last finished block does the finalize ----
    __shared__ bool s_last;
    __threadfence();
    if (tid == 0) {
        unsigned int old = atomicAdd(&g_done_count, 1u);
        s_last = (old == (unsigned int)(NBLKS - 1));
    }
    __syncthreads();
    if (!s_last) return;

    // Deterministic final combine (fixed-slot arrays, fixed-order tree).
    __shared__ float sred[256];
    __shared__ int   spred[256];
    float a = 0.f;
    #pragma unroll
    for (int k = 0; k < 3; k++) {
        int idx = tid + 256 * k;
        if (idx < NOBJ) a += g_obj_partial[idx];
    }
    a *= L_OBJ;
    int pp = 0;
    if (tid < NWIN) { a += g_loss_partial[tid]; pp = g_pos_partial[tid]; }
    sred[tid] = a;
    spred[tid] = pp;
    __syncthreads();
    #pragma unroll
    for (int s = 128; s > 0; s >>= 1) {
        if (tid < s) { sred[tid] += sred[tid + s]; spred[tid] += spred[tid + s]; }
        __syncthreads();
    }
    if (tid == 0) {
        out[0] = sred[0] / (float)max(spred[0], 1);
        g_done_count = 0;   // reset for next graph replay
    }
}

// ---------------------------------------------------------------------------
extern "C" void kernel_launch(void* const* d_in, const int* in_sizes, int n_in,
                              void* d_out, int out_size) {
    const float* p0       = (const float*)d_in[0];
    const float* p1       = (const float*)d_in[1];
    const float* p2       = (const float*)d_in[2];
    const float* body     = (const float*)d_in[3];
    const float* headb    = (const float*)d_in[4];
    const int*   labels   = (const int*)d_in[5];
    const int*   emotions = (const int*)d_in[6];
    const int*   actions  = (const int*)d_in[7];
    const int*   head_valid = (const int*)d_in[8];
    float* out = (float*)d_out;

    fused_loss_kernel<<<NBLKS, 256>>>(p0, p1, p2, body, headb,
                                      labels, emotions, actions, head_valid, out);
}

// round 4
// speedup vs baseline: 1.2479x; 1.0979x over previous
#include <cuda_runtime.h>
#include <math.h>

// ---------------- problem constants ----------------
#define BB   16     // batch
#define NN   24     // boxes per image
#define CC   149    // 1 obj + 2 xy + 2 wh + 4 head + 120 + 8 + 12
#define NBC  120
#define NEC  8
#define NAC  12
#define IGN_V (-100)
#define IMG  640.0f

#define L_OBJ  1.0f
#define L_BOX  5.0f
#define L_HEAD 2.0f
#define L_ATTR 1.0f

#define T0_CELLS (BB * 80 * 80)   // 102400
#define T1_CELLS (BB * 40 * 40)   // 25600
#define T2_CELLS (BB * 20 * 20)   // 6400
#define TOT_CELLS (T0_CELLS + T1_CELLS + T2_CELLS)  // 134400

#define NWIN   48                  // 3 scales * 16 batch
#define NOBJ   248                 // obj blocks -> total grid = 296 = 2 * 148 SMs
#define NBLKS  (NWIN + NOBJ)
#define OBJ_STRIDE (NOBJ * 256)    // 63488

// scratch (device globals; no allocations allowed)
__device__ float g_obj_partial[NOBJ];
__device__ float g_loss_partial[NWIN];
__device__ int   g_pos_partial[NWIN];
__device__ unsigned int g_done_count = 0;   // self-resets -> graph-replay safe

__device__ __forceinline__ float softplusf(float x) {
    return fmaxf(x, 0.f) + log1pf(expf(-fabsf(x)));
}
__device__ __forceinline__ float sigm(float x) { return 1.f / (1.f + expf(-x)); }
__device__ __forceinline__ float sl1(float p, float t) {
    float d = fabsf(p - t);
    return d < 1.f ? 0.5f * d * d : d - 0.5f;
}
__device__ __forceinline__ float wredf(float v) {
    #pragma unroll
    for (int o = 16; o > 0; o >>= 1) v += __shfl_xor_sync(0xffffffffu, v, o);
    return v;
}
__device__ __forceinline__ float wredmax(float v) {
    #pragma unroll
    for (int o = 16; o > 0; o >>= 1) v = fmaxf(v, __shfl_xor_sync(0xffffffffu, v, o));
    return v;
}

// ---------------------------------------------------------------------------
// Winner-loss role: one block per (scale, batch-row); 8 warps, 3 boxes/warp.
// All pred-independent per-box data precomputed in shared during setup.
// ---------------------------------------------------------------------------
__device__ void winner_loss_block(int blk,
                                  const float* __restrict__ p0,
                                  const float* __restrict__ p1,
                                  const float* __restrict__ p2,
                                  const float* __restrict__ body,
                                  const float* __restrict__ headb,
                                  const int*   __restrict__ labels,
                                  const int*   __restrict__ emotions,
                                  const int*   __restrict__ actions,
                                  const int*   __restrict__ head_valid) {
    const int s = blk / BB;
    const int b = blk % BB;
    const float* pred = (s == 0) ? p0 : ((s == 1) ? p1 : p2);
    const int   H  = (s == 0) ? 80 : ((s == 1) ? 40 : 20);
    const int   W  = H;
    const float sx = IMG / (float)W;
    const float sy = IMG / (float)H;

    __shared__ float sArea[NN];
    __shared__ float sTX[NN], sTY[NN], sTW[NN], sTH[NN];
    __shared__ float sQ0[NN], sQ1[NN], sQ2[NN], sQ3[NN];
    __shared__ int   sGX[NN], sGY[NN], sRank[NN];
    __shared__ int   sLab[NN], sEm[NN], sAc[NN];
    __shared__ unsigned char sValid[NN], sWin[NN], sHM[NN];

    const int tid  = threadIdx.x;
    const int warp = tid >> 5;
    const int lane = tid & 31;

    if (tid < NN) {
        const float* bx = body + ((size_t)b * NN + tid) * 4;
        float r0 = bx[0], r1 = bx[1], r2 = bx[2], r3 = bx[3];
        float mxv = fmaxf(fmaxf(r0, r1), fmaxf(r2, r3));
        float sc = (mxv <= 1.5f) ? IMG : 1.f;      // _scale_box
        float x1 = r0 * sc, y1 = r1 * sc, x2 = r2 * sc, y2 = r3 * sc;
        float bw = x2 - x1, bh = y2 - y1;
        float cx = 0.5f * (x1 + x2), cy = 0.5f * (y1 + y2);
        int gx = (int)floorf(cx / sx);
        int gy = (int)floorf(cy / sy);
        bool valid = (bw > 0.f) && (bh > 0.f) && (gx >= 0) && (gy >= 0) &&
                     (gx < W) && (gy < H);
        sArea[tid] = fmaxf(r2 - r0, 0.f) * fmaxf(r3 - r1, 0.f); // unscaled
        int gxc = min(max(gx, 0), W - 1);
        int gyc = min(max(gy, 0), H - 1);
        sGX[tid] = gxc; sGY[tid] = gyc;
        sValid[tid] = valid ? 1 : 0;

        // box targets (winner-only semantics: bw_s=bw, bh_s=bh when winner)
        sTX[tid] = cx / sx - (float)gx;
        sTY[tid] = cy / sy - (float)gy;
        sTW[tid] = logf(bw / sx + 1e-6f);
        sTH[tid] = logf(bh / sy + 1e-6f);

        // head targets
        const float* hb = headb + ((size_t)b * NN + tid) * 4;
        float h0 = hb[0], h1 = hb[1], h2 = hb[2], h3 = hb[3];
        float hm = fmaxf(fmaxf(h0, h1), fmaxf(h2, h3));
        float hc = (hm <= 1.5f) ? IMG : 1.f;
        float hx1 = h0 * hc, hy1 = h1 * hc, hx2 = h2 * hc, hy2 = h3 * hc;
        bool hmask = (head_valid[b * NN + tid] != 0) &&
                     (hx2 > hx1) && (hy2 > hy1);
        sHM[tid] = hmask ? 1 : 0;
        float ibw = 1.f / bw, ibh = 1.f / bh;   // only used when valid winner
        sQ0[tid] = fminf(fmaxf((hx1 - x1) * ibw, 0.f), 1.f);
        sQ1[tid] = fminf(fmaxf((hy1 - y1) * ibh, 0.f), 1.f);
        sQ2[tid] = fminf(fmaxf((hx2 - x1) * ibw, 0.f), 1.f);
        sQ3[tid] = fminf(fmaxf((hy2 - y1) * ibh, 0.f), 1.f);

        sLab[tid] = labels[b * NN + tid];
        sEm[tid]  = emotions[b * NN + tid];
        sAc[tid]  = actions[b * NN + tid];
    }
    __syncthreads();

    if (tid < NN) {
        // stable ascending argsort rank (double-argsort equivalent)
        float ai = sArea[tid];
        int r = 0;
        #pragma unroll
        for (int j = 0; j < NN; j++) {
            float aj = sArea[j];
            if (aj < ai || (aj == ai && j < tid)) r++;
        }
        sRank[tid] = r;
    }
    __syncthreads();

    if (tid < NN) {
        bool win = sValid[tid] != 0;
        if (win) {
            int gx = sGX[tid], gy = sGY[tid], ri = sRank[tid];
            #pragma unroll
            for (int j = 0; j < NN; j++) {
                if (sValid[j] && sGX[j] == gx && sGY[j] == gy && sRank[j] < ri)
                    win = false;
            }
        }
        sWin[tid] = win ? 1 : 0;
    }
    __syncthreads();

    float wloss = 0.f;
    int   wpos  = 0;

    for (int n = warp; n < NN; n += 8) {
        if (!sWin[n]) continue;
        wpos++;

        const float* cp = pred + (((size_t)b * H + sGY[n]) * W + sGX[n]) * CC;

        // ---- load all 149 channels warp-wide ----
        // head part: lanes 0..8 -> cp[0..8]
        float chd = (lane < 9) ? cp[lane] : 0.f;
        // attr part: j = lane + 32k, k=0..4 -> channels 9+j, j<140
        float v[5];
        #pragma unroll
        for (int k = 0; k < 5; k++) {
            int j = lane + 32 * k;
            v[k] = (j < NBC + NEC + NAC) ? cp[9 + j] : 0.f;
        }

        // ---- three group log-sum-exps (body j<120, emo 120..127, act 128..139)
        float mB = -1e30f, mE = -1e30f, mA = -1e30f;
        #pragma unroll
        for (int k = 0; k < 5; k++) {
            int j = lane + 32 * k;
            if (j < NBC)                    mB = fmaxf(mB, v[k]);
            else if (j < NBC + NEC)         mE = fmaxf(mE, v[k]);
            else if (j < NBC + NEC + NAC)   mA = fmaxf(mA, v[k]);
        }
        mB = wredmax(mB); mE = wredmax(mE); mA = wredmax(mA);
        float eB = 0.f, eE = 0.f, eA = 0.f;
        #pragma unroll
        for (int k = 0; k < 5; k++) {
            int j = lane + 32 * k;
            if (j < NBC)                    eB += expf(v[k] - mB);
            else if (j < NBC + NEC)         eE += expf(v[k] - mE);
            else if (j < NBC + NEC + NAC)   eA += expf(v[k] - mA);
        }
        eB = wredf(eB); eE = wredf(eE); eA = wredf(eA);

        // ---- per-lane box/head/obj contribution ----
        float contrib = 0.f;
        if (lane == 0)      contrib = -L_OBJ * chd;
        else if (lane == 1) contrib = L_BOX * sl1(sigm(chd), sTX[n]);
        else if (lane == 2) contrib = L_BOX * sl1(sigm(chd), sTY[n]);
        else if (lane == 3) contrib = L_BOX * sl1(chd, sTW[n]);
        else if (lane == 4) contrib = L_BOX * sl1(chd, sTH[n]);
        else if (lane < 9 && sHM[n]) {
            float q = (lane == 5) ? sQ0[n] : (lane == 6) ? sQ1[n]
                    : (lane == 7) ? sQ2[n] : sQ3[n];
            contrib = L_HEAD * sl1(sigm(chd), q);
        }
        contrib = wredf(contrib);

        // ---- CE terms (uniform across warp; target logit via broadcast load)
        float ce = 0.f;
        int lab = sLab[n];
        if (lab != IGN_V) {
            int t = min(max(lab, 0), NBC - 1);
            ce += -(cp[9 + t] - mB - logf(eB));
        }
        int em = sEm[n];
        if (em != IGN_V) {
            int t = min(max(em, 0), NEC - 1);
            ce += -(cp[9 + NBC + t] - mE - logf(eE));
        }
        int ac = sAc[n];
        if (ac != IGN_V) {
            int t = min(max(ac, 0), NAC - 1);
            ce += -(cp[9 + NBC + NEC + t] - mA - logf(eA));
        }
        if (lane == 0) wloss += contrib + L_ATTR * ce;
    }

    // deterministic block reduction over the 8 warps
    __shared__ float shl[8];
    __shared__ int   shp[8];
    if (lane == 0) { shl[warp] = wloss; shp[warp] = wpos; }
    __syncthreads();
    if (tid == 0) {
        float L = 0.f; int P = 0;
        #pragma unroll
        for (int w = 0; w < 8; w++) { L += shl[w]; P += shp[w]; }
        g_loss_partial[blk] = L;
        g_pos_partial[blk]  = P;
    }
}

// ---------------------------------------------------------------------------
// Fused kernel: blocks [0,48) winner losses, blocks [48,296) obj softplus sum
// with 3 cells/thread (front-batched LDGs). Last block finalizes.
// ---------------------------------------------------------------------------
__global__ void __launch_bounds__(256)
fused_loss_kernel(const float* __restrict__ p0,
                  const float* __restrict__ p1,
                  const float* __restrict__ p2,
                  const float* __restrict__ body,
                  const float* __restrict__ headb,
                  const int*   __restrict__ labels,
                  const int*   __restrict__ emotions,
                  const int*   __restrict__ actions,
                  const int*   __restrict__ head_valid,
                  float* __restrict__ out) {
    const int tid = threadIdx.x;

    if (blockIdx.x < NWIN) {
        winner_loss_block(blockIdx.x, p0, p1, p2, body, headb,
                          labels, emotions, actions, head_valid);
    } else {
        const int g = (blockIdx.x - NWIN) * 256 + tid;
        // three independent cells -> MLP=3, front-batched
        float x[3];
        #pragma unroll
        for (int k = 0; k < 3; k++) {
            int i = g + k * OBJ_STRIDE;
            const float* p; int loc;
            if (i < T0_CELLS)                  { p = p0; loc = i; }
            else if (i < T0_CELLS + T1_CELLS)  { p = p1; loc = i - T0_CELLS; }
            else                               { p = p2; loc = i - T0_CELLS - T1_CELLS; }
            bool ok = (i < TOT_CELLS);
            x[k] = ok ? __ldg(p + (size_t)loc * CC) : 0.f;
            if (!ok) x[k] = -1e30f;   // softplus(-inf)=0 handled below
        }
        float acc = 0.f;
        #pragma unroll
        for (int k = 0; k < 3; k++) {
            int i = g + k * OBJ_STRIDE;
            if (i < TOT_CELLS) acc += softplusf(x[k]);
        }
        acc = wredf(acc);

        __shared__ float sh[8];
        if ((tid & 31) == 0) sh[tid >> 5] = acc;
        __syncthreads();
        if (tid == 0) {
            float t = 0.f;
            #pragma unroll
            for (int w = 0; w < 8; w++) t += sh[w];
            g_obj_partial[blockIdx.x - NWIN] = t;
        }
    }

    // ---- completion protocol: last finished block does the finalize ----
    __shared__ bool s_last;
    __threadfence();
    if (tid == 0) {
        unsigned int old = atomicAdd(&g_done_count, 1u);
        s_last = (old == (unsigned int)(NBLKS - 1));
    }
    __syncthreads();
    if (!s_last) return;

    // Deterministic final combine (fixed-slot arrays, fixed-order tree).
    __shared__ float sred[256];
    __shared__ int   spred[256];
    float a = 0.f;
    if (tid < NOBJ) a += g_obj_partial[tid];
    a *= L_OBJ;
    int pp = 0;
    if (tid < NWIN) { a += g_loss_partial[tid]; pp = g_pos_partial[tid]; }
    sred[tid] = a;
    spred[tid] = pp;
    __syncthreads();
    #pragma unroll
    for (int s = 128; s > 0; s >>= 1) {
        if (tid < s) { sred[tid] += sred[tid + s]; spred[tid] += spred[tid + s]; }
        __syncthreads();
    }
    if (tid == 0) {
        out[0] = sred[0] / (float)max(spred[0], 1);
        g_done_count = 0;   // reset for next graph replay
    }
}

// ---------------------------------------------------------------------------
extern "C" void kernel_launch(void* const* d_in, const int* in_sizes, int n_in,
                              void* d_out, int out_size) {
    const float* p0       = (const float*)d_in[0];
    const float* p1       = (const float*)d_in[1];
    const float* p2       = (const float*)d_in[2];
    const float* body     = (const float*)d_in[3];
    const float* headb    = (const float*)d_in[4];
    const int*   labels   = (const int*)d_in[5];
    const int*   emotions = (const int*)d_in[6];
    const int*   actions  = (const int*)d_in[7];
    const int*   head_valid = (const int*)d_in[8];
    float* out = (float*)d_out;

    fused_loss_kernel<<<NBLKS, 256>>>(p0, p1, p2, body, headb,
                                      labels, emotions, actions, head_valid, out);
}

// round 5
// speedup vs baseline: 1.7413x; 1.3953x over previous
#include <cuda_runtime.h>
#include <math.h>

// ---------------- problem constants ----------------
#define BB   16     // batch
#define NN   24     // boxes per image
#define CC   149    // 1 obj + 2 xy + 2 wh + 4 head + 120 + 8 + 12
#define NBC  120
#define NEC  8
#define NAC  12
#define IGN_V (-100)
#define IMG  640.0f

#define L_OBJ  1.0f
#define L_BOX  5.0f
#define L_HEAD 2.0f
#define L_ATTR 1.0f

#define T0_CELLS (BB * 80 * 80)   // 102400
#define T1_CELLS (BB * 40 * 40)   // 25600
#define T2_CELLS (BB * 20 * 20)   // 6400
#define TOT_CELLS (T0_CELLS + T1_CELLS + T2_CELLS)  // 134400

#define NWINB  144                 // winner blocks: 144*8 warps = 1152 = 3*16*24
#define NOBJB  152                 // obj blocks
#define NBLKS  (NWINB + NOBJB)     // 296 = 2 * 148 SMs
#define OBJ_STRIDE (NOBJB * 256)   // 38912; 4 cells/thread covers 155648 >= 134400

// scratch (device globals; no allocations allowed)
__device__ float g_obj_partial[NOBJB];
__device__ float g_loss_partial[NWINB];
__device__ int   g_pos_partial[NWINB];
__device__ unsigned int g_done_count = 0;   // self-resets -> graph-replay safe

__device__ __forceinline__ float softplusf(float x) {
    return fmaxf(x, 0.f) + log1pf(expf(-fabsf(x)));
}
__device__ __forceinline__ float sigm(float x) { return 1.f / (1.f + expf(-x)); }
__device__ __forceinline__ float sl1(float p, float t) {
    float d = fabsf(p - t);
    return d < 1.f ? 0.5f * d * d : d - 0.5f;
}
__device__ __forceinline__ float wredf(float v) {
    #pragma unroll
    for (int o = 16; o > 0; o >>= 1) v += __shfl_xor_sync(0xffffffffu, v, o);
    return v;
}
__device__ __forceinline__ float wredmax(float v) {
    #pragma unroll
    for (int o = 16; o > 0; o >>= 1) v = fmaxf(v, __shfl_xor_sync(0xffffffffu, v, o));
    return v;
}

// ---------------------------------------------------------------------------
// Winner role: ONE WARP per (scale, batch, box). No serialization.
// ---------------------------------------------------------------------------
__device__ void winner_warp(int gwarp,
                            const float* __restrict__ p0,
                            const float* __restrict__ p1,
                            const float* __restrict__ p2,
                            const float* __restrict__ body,
                            const float* __restrict__ headb,
                            const int*   __restrict__ labels,
                            const int*   __restrict__ emotions,
                            const int*   __restrict__ actions,
                            const int*   __restrict__ head_valid,
                            float* wloss_out, int* wpos_out) {
    const unsigned FULL = 0xffffffffu;
    const int s   = gwarp / (BB * NN);
    const int rem = gwarp % (BB * NN);
    const int b   = rem / NN;
    const int n   = rem % NN;
    const int lane = threadIdx.x & 31;

    const float* pred = (s == 0) ? p0 : ((s == 1) ? p1 : p2);
    const int   H  = (s == 0) ? 80 : ((s == 1) ? 40 : 20);
    const int   W  = H;
    const float sx = IMG / (float)W;
    const float sy = IMG / (float)H;

    // ---- round 1: all independent loads issued together ----
    float4 bb4 = make_float4(0.f, 0.f, 0.f, 0.f);
    float4 hb4 = make_float4(0.f, 0.f, 0.f, 0.f);
    if (lane < NN) {
        bb4 = __ldg((const float4*)(body  + ((size_t)b * NN + lane) * 4));
        hb4 = __ldg((const float4*)(headb + ((size_t)b * NN + lane) * 4));
    }
    const int lab = __ldg(labels     + b * NN + n);
    const int em  = __ldg(emotions   + b * NN + n);
    const int ac  = __ldg(actions    + b * NN + n);
    const int hv  = __ldg(head_valid + b * NN + n);

    // ---- per-lane box geometry (lane j = box j of this row) ----
    float mxv = fmaxf(fmaxf(bb4.x, bb4.y), fmaxf(bb4.z, bb4.w));
    float sc  = (mxv <= 1.5f) ? IMG : 1.f;       // _scale_box
    float x1 = bb4.x * sc, y1 = bb4.y * sc, x2 = bb4.z * sc, y2 = bb4.w * sc;
    float bw = x2 - x1, bh = y2 - y1;
    float cx = 0.5f * (x1 + x2), cy = 0.5f * (y1 + y2);
    int gx = (int)floorf(cx / sx);
    int gy = (int)floorf(cy / sy);
    int valid = (lane < NN) && (bw > 0.f) && (bh > 0.f) &&
                (gx >= 0) && (gy >= 0) && (gx < W) && (gy < H);
    float area = fmaxf(bb4.z - bb4.x, 0.f) * fmaxf(bb4.w - bb4.y, 0.f); // unscaled
    int gxc = min(max(gx, 0), W - 1);
    int gyc = min(max(gy, 0), H - 1);
    int cell = gyc * W + gxc;

    // ---- winner test for box n via ballot ----
    float area_n = __shfl_sync(FULL, area, n);
    int   cell_n = __shfl_sync(FULL, cell, n);
    int   valid_n = __shfl_sync(FULL, valid, n);
    bool beat = (lane < NN) && (lane != n) && valid && (cell == cell_n) &&
                (area < area_n || (area == area_n && lane < n));
    bool win = valid_n && (__ballot_sync(FULL, beat) == 0u);

    *wloss_out = 0.f;
    *wpos_out  = 0;
    if (!win) return;

    // box-n geometry broadcast
    float x1n = __shfl_sync(FULL, x1, n);
    float y1n = __shfl_sync(FULL, y1, n);
    float bwn = __shfl_sync(FULL, bw, n);
    float bhn = __shfl_sync(FULL, bh, n);
    float cxn = __shfl_sync(FULL, cx, n);
    float cyn = __shfl_sync(FULL, cy, n);
    int   gxn = __shfl_sync(FULL, gx, n);
    int   gyn = __shfl_sync(FULL, gy, n);

    // head-n geometry
    float hmv = fmaxf(fmaxf(hb4.x, hb4.y), fmaxf(hb4.z, hb4.w));
    float hsc = (hmv <= 1.5f) ? IMG : 1.f;
    float hx1 = hb4.x * hsc, hy1 = hb4.y * hsc, hx2 = hb4.z * hsc, hy2 = hb4.w * hsc;
    float hx1n = __shfl_sync(FULL, hx1, n);
    float hy1n = __shfl_sync(FULL, hy1, n);
    float hx2n = __shfl_sync(FULL, hx2, n);
    float hy2n = __shfl_sync(FULL, hy2, n);
    bool hmask = (hv != 0) && (hx2n > hx1n) && (hy2n > hy1n);

    // ---- round 2: pred channel loads (warp-wide) ----
    const float* cp = pred + (((size_t)b * H + gyn) * W + gxn) * CC;
    float chd = (lane < 9) ? __ldg(cp + lane) : 0.f;
    float v[5];
    #pragma unroll
    for (int k = 0; k < 5; k++) {
        int j = lane + 32 * k;
        v[k] = (j < NBC + NEC + NAC) ? __ldg(cp + 9 + j) : 0.f;
    }

    // ---- three group log-sum-exps ----
    float mB = -1e30f, mE = -1e30f, mA = -1e30f;
    #pragma unroll
    for (int k = 0; k < 5; k++) {
        int j = lane + 32 * k;
        if (j < NBC)                  mB = fmaxf(mB, v[k]);
        else if (j < NBC + NEC)       mE = fmaxf(mE, v[k]);
        else if (j < NBC + NEC + NAC) mA = fmaxf(mA, v[k]);
    }
    mB = wredmax(mB); mE = wredmax(mE); mA = wredmax(mA);
    float eB = 0.f, eE = 0.f, eA = 0.f;
    #pragma unroll
    for (int k = 0; k < 5; k++) {
        int j = lane + 32 * k;
        if (j < NBC)                  eB += expf(v[k] - mB);
        else if (j < NBC + NEC)       eE += expf(v[k] - mE);
        else if (j < NBC + NEC + NAC) eA += expf(v[k] - mA);
    }
    eB = wredf(eB); eE = wredf(eE); eA = wredf(eA);

    // ---- per-lane box/head/obj contributions ----
    float contrib = 0.f;
    if (lane == 0)      contrib = -L_OBJ * chd;
    else if (lane == 1) contrib = L_BOX * sl1(sigm(chd), cxn / sx - (float)gxn);
    else if (lane == 2) contrib = L_BOX * sl1(sigm(chd), cyn / sy - (float)gyn);
    else if (lane == 3) contrib = L_BOX * sl1(chd, logf(bwn / sx + 1e-6f));
    else if (lane == 4) contrib = L_BOX * sl1(chd, logf(bhn / sy + 1e-6f));
    else if (lane < 9 && hmask) {
        float ibw = 1.f / bwn, ibh = 1.f / bhn;
        float q = (lane == 5) ? (hx1n - x1n) * ibw
                : (lane == 6) ? (hy1n - y1n) * ibh
                : (lane == 7) ? (hx2n - x1n) * ibw
                :               (hy2n - y1n) * ibh;
        q = fminf(fmaxf(q, 0.f), 1.f);
        contrib = L_HEAD * sl1(sigm(chd), q);
    }
    contrib = wredf(contrib);

    // ---- CE terms (uniform broadcast loads; lines already in L1) ----
    float ce = 0.f;
    if (lab != IGN_V) {
        int t = min(max(lab, 0), NBC - 1);
        ce += -(__ldg(cp + 9 + t) - mB - logf(eB));
    }
    if (em != IGN_V) {
        int t = min(max(em, 0), NEC - 1);
        ce += -(__ldg(cp + 9 + NBC + t) - mE - logf(eE));
    }
    if (ac != IGN_V) {
        int t = min(max(ac, 0), NAC - 1);
        ce += -(__ldg(cp + 9 + NBC + NEC + t) - mA - logf(eA));
    }

    *wloss_out = contrib + L_ATTR * ce;
    *wpos_out  = 1;
}

// ---------------------------------------------------------------------------
// Fused kernel: blocks [0,144) = 8 winner-warps each; blocks [144,296) = obj
// softplus sum, 4 front-batched cells/thread. Last finished block finalizes.
// ---------------------------------------------------------------------------
__global__ void __launch_bounds__(256)
fused_loss_kernel(const float* __restrict__ p0,
                  const float* __restrict__ p1,
                  const float* __restrict__ p2,
                  const float* __restrict__ body,
                  const float* __restrict__ headb,
                  const int*   __restrict__ labels,
                  const int*   __restrict__ emotions,
                  const int*   __restrict__ actions,
                  const int*   __restrict__ head_valid,
                  float* __restrict__ out) {
    const int tid  = threadIdx.x;
    const int warp = tid >> 5;
    const int lane = tid & 31;

    if (blockIdx.x < NWINB) {
        float wl; int wp;
        winner_warp(blockIdx.x * 8 + warp, p0, p1, p2, body, headb,
                    labels, emotions, actions, head_valid, &wl, &wp);
        // deterministic per-block reduce over 8 warps (lane 0 holds values)
        __shared__ float shl[8];
        __shared__ int   shp[8];
        if (lane == 0) { shl[warp] = wl; shp[warp] = wp; }
        __syncthreads();
        if (tid == 0) {
            float L = 0.f; int P = 0;
            #pragma unroll
            for (int w = 0; w < 8; w++) { L += shl[w]; P += shp[w]; }
            g_loss_partial[blockIdx.x] = L;
            g_pos_partial[blockIdx.x]  = P;
        }
    } else {
        const int g = (blockIdx.x - NWINB) * 256 + tid;
        // four independent cells -> MLP=4, front-batched
        float x[4];
        #pragma unroll
        for (int k = 0; k < 4; k++) {
            int i = g + k * OBJ_STRIDE;
            const float* p; int loc;
            if (i < T0_CELLS)                  { p = p0; loc = i; }
            else if (i < T0_CELLS + T1_CELLS)  { p = p1; loc = i - T0_CELLS; }
            else                               { p = p2; loc = i - T0_CELLS - T1_CELLS; }
            x[k] = (i < TOT_CELLS) ? __ldg(p + (size_t)loc * CC) : -1e30f;
        }
        float acc = 0.f;
        #pragma unroll
        for (int k = 0; k < 4; k++) {
            int i = g + k * OBJ_STRIDE;
            if (i < TOT_CELLS) acc += softplusf(x[k]);
        }
        acc = wredf(acc);

        __shared__ float sh[8];
        if (lane == 0) sh[warp] = acc;
        __syncthreads();
        if (tid == 0) {
            float t = 0.f;
            #pragma unroll
            for (int w = 0; w < 8; w++) t += sh[w];
            g_obj_partial[blockIdx.x - NWINB] = t;
        }
    }

    // ---- completion protocol: last finished block does the finalize ----
    __shared__ bool s_last;
    __threadfence();
    if (tid == 0) {
        unsigned int old = atomicAdd(&g_done_count, 1u);
        s_last = (old == (unsigned int)(NBLKS - 1));
    }
    __syncthreads();
    if (!s_last) return;

    // Deterministic final combine (fixed-slot arrays, fixed-order tree).
    __shared__ float sred[256];
    __shared__ int   spred[256];
    float a = 0.f;
    if (tid < NOBJB) a = L_OBJ * g_obj_partial[tid];
    int pp = 0;
    if (tid < NWINB) { a += g_loss_partial[tid]; pp = g_pos_partial[tid]; }
    sred[tid]  = a;
    spred[tid] = pp;
    __syncthreads();
    #pragma unroll
    for (int s = 128; s > 0; s >>= 1) {
        if (tid < s) { sred[tid] += sred[tid + s]; spred[tid] += spred[tid + s]; }
        __syncthreads();
    }
    if (tid == 0) {
        out[0] = sred[0] / (float)max(spred[0], 1);
        g_done_count = 0;   // reset for next graph replay
    }
}

// ---------------------------------------------------------------------------
extern "C" void kernel_launch(void* const* d_in, const int* in_sizes, int n_in,
                              void* d_out, int out_size) {
    const float* p0       = (const float*)d_in[0];
    const float* p1       = (const float*)d_in[1];
    const float* p2       = (const float*)d_in[2];
    const float* body     = (const float*)d_in[3];
    const float* headb    = (const float*)d_in[4];
    const int*   labels   = (const int*)d_in[5];
    const int*   emotions = (const int*)d_in[6];
    const int*   actions  = (const int*)d_in[7];
    const int*   head_valid = (const int*)d_in[8];
    float* out = (float*)d_out;

    fused_loss_kernel<<<NBLKS, 256>>>(p0, p1, p2, body, headb,
                                      labels, emotions, actions, head_valid, out);
}